// round 14
// baseline (speedup 1.0000x reference)
#include <cuda_runtime.h>
#include <cuda_bf16.h>

// ---------------------------------------------------------------------------
// Tagger: 2-layer bidirectional LSTM (B=S=512, E=20, H1=30, H2=50, NTAGS=45)
// Reference quirk: (S,B,H)->(B,S,H) reshape with S==B is an index swap.
// Storage convention (all [time][batch][h]):
//   F1[t][b], B1[t][b]  : layer-1 hidden at time t, batch b
//   layer-2 row rho consumes at step u: ( F1[rho][u], B1[511-rho][u] )
//   F2 stored [u][rho]; B2 stored [511-u][rho]  =>  OUT reads both at [i][j].
//
// Hoisted: TG[dir][tok][j][4]   = Wih1·emb[tok]  (gate-interleaved, float4)
//          XG[dir][pos][200]    = Wih2·(F1,B1)   (gate-blocked: [i|f|g|o]x50)
// r1: 2 rows/block, 128 thr, 4 blocks/SM, shared-combine, 2 barriers (281us).
// r2: 296 blocks (2/SM), 4-or-3 rows, 224 thr, thread-per-gate (575us).
// out: F2/B2 rows staged through shared (coalesced) then register-resident.
// ---------------------------------------------------------------------------

typedef unsigned long long u64;

__device__ float g_F1[512 * 512 * 30];
__device__ float g_B1[512 * 512 * 30];
__device__ float g_F2[512 * 512 * 50];
__device__ float g_B2[512 * 512 * 50];
__device__ float g_TGf[50000 * 120];
__device__ float g_TGb[50000 * 120];
__device__ float g_XGf[512 * 512 * 200];
__device__ float g_XGb[512 * 512 * 200];
__device__ int   g_is64;

__device__ __forceinline__ void fma2(u64 &acc, u64 a, u64 b) {
    asm("fma.rn.f32x2 %0, %1, %2, %0;" : "+l"(acc) : "l"(a), "l"(b));
}
__device__ __forceinline__ float2 up2(u64 v) {
    float2 r; asm("mov.b64 {%0, %1}, %2;" : "=f"(r.x), "=f"(r.y) : "l"(v));
    return r;
}
__device__ __forceinline__ u64 pack2(float a, float b) {
    u64 r; asm("mov.b64 %0, {%1, %2};" : "=l"(r) : "f"(a), "f"(b));
    return r;
}

__device__ __forceinline__ float sigm(float x) {
    return __fdividef(1.f, 1.f + __expf(-x));
}
__device__ __forceinline__ float tanh_f(float x) {
    float a = fabsf(x);
    float e = __expf(-2.f * a);
    float t = __fdividef(1.f - e, 1.f + e);
    return x < 0.f ? -t : t;
}

// ---------------------------------------------------------------------------
// Token gate table (one dir per launch):
//   TG[dir][tok][j*4 + g] = Wih1[dir][g*30+j] · emb[dir][tok]
// dir==0 launch also performs the int64/int32 dtype sniff on x.
// ---------------------------------------------------------------------------
__global__ void __launch_bounds__(256) tokgate_kernel(
    const float* __restrict__ emb, const float* __restrict__ Wih,
    const int* __restrict__ x, int dir, int nvocab)
{
    if (dir == 0 && blockIdx.x == 0 && threadIdx.x == 0) {
        int z = 0;
        for (int i = 1; i < 256; i += 2) z |= x[i];
        g_is64 = (z == 0) ? 1 : 0;
    }
    float* TG = dir ? g_TGb : g_TGf;

    __shared__ __align__(16) float e_sh[256][20];
    const int tid = threadIdx.x;
    const int base = blockIdx.x * 256;
    for (int idx = tid; idx < 256 * 20; idx += 256) {
        int tl = idx / 20, k = idx - tl * 20;
        int tok = base + tl;
        e_sh[tl][k] = (tok < nvocab) ? emb[tok * 20 + k] : 0.f;
    }
    __syncthreads();
    if (tid < 120) {
        const int g = tid / 30, j = tid - g * 30;
        u64 w2[10];
        const u64* wa = (const u64*)(Wih + tid * 20);
#pragma unroll
        for (int k = 0; k < 10; k++) w2[k] = wa[k];
        int nmax = nvocab - base; if (nmax > 256) nmax = 256;
        for (int tl = 0; tl < nmax; tl++) {
            const ulonglong2* xs = (const ulonglong2*)e_sh[tl];
            u64 ac0 = 0, ac1 = 0, ac2 = 0, ac3 = 0;
#pragma unroll
            for (int q = 0; q < 5; q++) {
                ulonglong2 v = xs[q];
                if (q & 1) { fma2(ac2, v.x, w2[2 * q]); fma2(ac3, v.y, w2[2 * q + 1]); }
                else        { fma2(ac0, v.x, w2[2 * q]); fma2(ac1, v.y, w2[2 * q + 1]); }
            }
            float2 f0 = up2(ac0), f1 = up2(ac1), f2 = up2(ac2), f3 = up2(ac3);
            TG[(base + tl) * 120 + j * 4 + g] = ((f0.x + f0.y) + (f1.x + f1.y))
                                              + ((f2.x + f2.y) + (f3.x + f3.y));
        }
    }
}

// ---------------------------------------------------------------------------
// Layer 1 scan: 512 blocks (2 dirs x 256), 2 batch rows/block, 128 threads,
// 4 blocks/SM, shared-combine, 2 barriers.
// ---------------------------------------------------------------------------
__global__ void __launch_bounds__(128, 4) r1_kernel(
    const int* __restrict__ x,
    const float* __restrict__ h0f, const float* __restrict__ c0f,
    const float* __restrict__ Whhf,
    const float* __restrict__ bihf, const float* __restrict__ bhhf,
    const float* __restrict__ h0b, const float* __restrict__ c0b,
    const float* __restrict__ Whhb,
    const float* __restrict__ bihb, const float* __restrict__ bhhb)
{
    const int dir = blockIdx.x >> 8;           // 0 = forward, 1 = backward
    const int rowBase = (blockIdx.x & 255) * 2;
    const float* Whh = dir ? Whhb : Whhf;
    const float* bih = dir ? bihb : bihf;
    const float* bhh = dir ? bhhb : bhhf;
    const float* h0  = dir ? h0b  : h0f;
    const float* c0  = dir ? c0b  : c0f;
    const float* TG  = dir ? g_TGb : g_TGf;
    float* outp = dir ? g_B1 : g_F1;

    const int tid = threadIdx.x;
    __shared__ __align__(16) float h_sh[2][2][32];
    __shared__ float hg_sh[2][120];

    const bool isH = (tid < 120);
    u64 whh2[15];
    float bias = 0.f;
    if (isH) {
        const u64* wb = (const u64*)(Whh + tid * 30);   // 120B rows, 8B-aligned
#pragma unroll
        for (int k = 0; k < 15; k++) whh2[k] = wb[k];
        bias = bih[tid] + bhh[tid];
    }
    for (int idx = tid; idx < 2 * 32; idx += 128) {
        int r = idx >> 5, k = idx & 31;
        h_sh[0][r][k] = (k < 30) ? h0[(rowBase + r) * 30 + k] : 0.f;
        h_sh[1][r][k] = 0.f;
    }
    // combine: task m = tid in [0,60): r = m/30, j = m%30
    const int r0 = tid / 30, j0 = tid - r0 * 30;
    const bool isC = (tid < 60);
    const int row0 = rowBase + r0;
    const int is64 = g_is64;
    float cc0 = isC ? c0[row0 * 30 + j0] : 0.f;

    // prefetch token gates for step 0 (one float4, gate-interleaved TG)
    float4 tg = make_float4(0.f, 0.f, 0.f, 0.f);
    if (isC) {
        int t0 = dir ? 511 : 0;
        int i0 = row0 * 512 + t0;
        int tok = x[is64 ? 2 * i0 : i0];
        tg = *(const float4*)&TG[tok * 120 + j0 * 4];
    }
    __syncthreads();

    int cur = 0;
    for (int s = 0; s < 512; s++) {
        const int t = dir ? (511 - s) : s;
        float4 ntg = make_float4(0.f, 0.f, 0.f, 0.f);
        if (s < 511 && isC) {
            int tn = dir ? (510 - s) : (s + 1);
            int in = row0 * 512 + tn;
            int tok = x[is64 ? 2 * in : in];
            ntg = *(const float4*)&TG[tok * 120 + j0 * 4];
        }
        if (isH) {
#pragma unroll
            for (int r = 0; r < 2; r++) {
                const ulonglong2* hs = (const ulonglong2*)h_sh[cur][r];
                u64 ac0 = 0, ac1 = 0, ac2 = 0, ac3 = 0;
#pragma unroll
                for (int q = 0; q < 7; q++) {
                    ulonglong2 v = hs[q];
                    if (q & 1) { fma2(ac2, v.x, whh2[2 * q]); fma2(ac3, v.y, whh2[2 * q + 1]); }
                    else        { fma2(ac0, v.x, whh2[2 * q]); fma2(ac1, v.y, whh2[2 * q + 1]); }
                }
                {
                    u64 tpair = *(const u64*)&h_sh[cur][r][28];
                    fma2(ac2, tpair, whh2[14]);
                }
                float2 f0 = up2(ac0), f1 = up2(ac1), f2 = up2(ac2), f3 = up2(ac3);
                hg_sh[r][tid] = bias + ((f0.x + f0.y) + (f1.x + f1.y))
                                     + ((f2.x + f2.y) + (f3.x + f3.y));
            }
        }
        __syncthreads();
        if (isC) {
            float gi = tg.x + hg_sh[r0][j0];
            float gf = tg.y + hg_sh[r0][30 + j0];
            float gg = tg.z + hg_sh[r0][60 + j0];
            float go = tg.w + hg_sh[r0][90 + j0];
            cc0 = sigm(gf) * cc0 + sigm(gi) * tanh_f(gg);
            float hh = sigm(go) * tanh_f(cc0);
            h_sh[cur ^ 1][r0][j0] = hh;
            outp[((size_t)t * 512 + row0) * 30 + j0] = hh;
        }
        __syncthreads();
        tg = ntg;
        cur ^= 1;
    }
}

// ---------------------------------------------------------------------------
// Layer-2 input gates: XG[pos][tid] = Wih2[tid] · (F1[rho][u], B1[511-rho][u])
// grid = 8192: dir = bx>>12, rho = (bx&4095)>>3, u-chunk = (bx&7)*64
// ---------------------------------------------------------------------------
__global__ void __launch_bounds__(256) xg2_kernel(
    const float* __restrict__ Wihf, const float* __restrict__ Wihb)
{
    const int bx = blockIdx.x;
    const int dir = bx >> 12;
    const int rem = bx & 4095;
    const int rho = rem >> 3;
    const int u0  = (rem & 7) * 64;
    const float* Wih = dir ? Wihb : Wihf;
    float* XG = dir ? g_XGb : g_XGf;

    __shared__ __align__(16) float x_sh[64][60];
    __shared__ __align__(16) float stage_sh[16][200];
    const int tid = threadIdx.x;
    const float* f1 = g_F1 + ((size_t)rho * 512 + u0) * 30;
    const float* b1 = g_B1 + ((size_t)(511 - rho) * 512 + u0) * 30;
    for (int idx = tid; idx < 1920; idx += 256) {
        int r = idx / 30, k = idx - r * 30;
        x_sh[r][k]      = f1[idx];
        x_sh[r][30 + k] = b1[idx];
    }

    u64 w2[30];
    if (tid < 200) {
        const u64* wa = (const u64*)(Wih + tid * 60);
#pragma unroll
        for (int k = 0; k < 30; k++) w2[k] = wa[k];
    }
    __syncthreads();

    float* outbase = XG + ((size_t)rho * 512 + u0) * 200;
#pragma unroll 1
    for (int c = 0; c < 4; c++) {
        if (tid < 200) {
#pragma unroll 2
            for (int p = 0; p < 16; p++) {
                const ulonglong2* xs = (const ulonglong2*)x_sh[c * 16 + p];
                u64 ac0 = 0, ac1 = 0, ac2 = 0, ac3 = 0;
#pragma unroll
                for (int q = 0; q < 15; q++) {
                    ulonglong2 v = xs[q];
                    if (q & 1) { fma2(ac2, v.x, w2[2 * q]); fma2(ac3, v.y, w2[2 * q + 1]); }
                    else        { fma2(ac0, v.x, w2[2 * q]); fma2(ac1, v.y, w2[2 * q + 1]); }
                }
                float2 f0 = up2(ac0), f1v = up2(ac1), f2 = up2(ac2), f3 = up2(ac3);
                stage_sh[p][tid] = ((f0.x + f0.y) + (f1v.x + f1v.y))
                                 + ((f2.x + f2.y) + (f3.x + f3.y));
            }
        }
        __syncthreads();
        float* ob = outbase + (size_t)(c * 16) * 200;
        for (int idx = tid; idx < 3200; idx += 256) {
            ob[idx] = ((const float*)stage_sh)[idx];
        }
        __syncthreads();
    }
}

// ---------------------------------------------------------------------------
// Layer 2 scan (round-12 proven config): 296 blocks (2 dirs x 148 = 2/SM),
// 4-or-3 rows/block, 224 threads, thread-per-gate.
// ---------------------------------------------------------------------------
__global__ void __launch_bounds__(224, 2) r2_kernel(
    const float* __restrict__ h0f, const float* __restrict__ c0f,
    const float* __restrict__ Whhf,
    const float* __restrict__ bihf, const float* __restrict__ bhhf,
    const float* __restrict__ h0b, const float* __restrict__ c0b,
    const float* __restrict__ Whhb,
    const float* __restrict__ bihb, const float* __restrict__ bhhb)
{
    const int dir = (blockIdx.x >= 148) ? 1 : 0;
    const int b   = blockIdx.x - dir * 148;
    const int rowBase = 3 * b + (b < 68 ? b : 68);
    const int nrows   = (b < 68) ? 4 : 3;
    const float* Whh = dir ? Whhb : Whhf;
    const float* bih = dir ? bihb : bihf;
    const float* bhh = dir ? bhhb : bhhf;
    const float* h0  = dir ? h0b  : h0f;
    const float* c0  = dir ? c0b  : c0f;
    const float* XG  = dir ? g_XGb : g_XGf;

    const int tid = threadIdx.x;
    __shared__ __align__(16) float h_sh[2][4][52];
    __shared__ float hg_sh[4][200];

    const bool isH = (tid < 200);
    u64 whh2[25];
    float bias = 0.f;
    if (isH) {
        const u64* wb = (const u64*)(Whh + tid * 50);   // 200B rows, 8B-aligned
#pragma unroll
        for (int k = 0; k < 25; k++) whh2[k] = wb[k];
        bias = bih[tid] + bhh[tid];
    }
    for (int idx = tid; idx < 4 * 52; idx += 224) {
        int r = idx / 52, k = idx - r * 52;
        h_sh[0][r][k] = (r < nrows && k < 50) ? h0[(rowBase + r) * 50 + k] : 0.f;
        h_sh[1][r][k] = 0.f;
    }
    // combine: task m = tid in [0,200): r = m/50, j = m%50
    const int r0 = tid / 50, j0 = tid - r0 * 50;
    const bool isC = (tid < 200) && (r0 < nrows);
    float cc0 = isC ? c0[(rowBase + r0) * 50 + j0] : 0.f;
    const size_t xb0 = isC ? ((size_t)(rowBase + r0) * 512) * 200 + j0 : 0;

    // prefetch XG for step 0
    float xg0[4] = {0,0,0,0};
    if (isC) {
        int u0 = dir ? 511 : 0;
#pragma unroll
        for (int g = 0; g < 4; g++) xg0[g] = XG[xb0 + (size_t)u0 * 200 + g * 50];
    }
    __syncthreads();

    int cur = 0;
    for (int s = 0; s < 512; s++) {
        const int u = dir ? (511 - s) : s;
        float nxg0[4] = {0,0,0,0};
        if (s < 511 && isC) {
            int un = dir ? (510 - s) : (s + 1);
#pragma unroll
            for (int g = 0; g < 4; g++) nxg0[g] = XG[xb0 + (size_t)un * 200 + g * 50];
        }
        if (isH) {
#pragma unroll
            for (int r = 0; r < 4; r++) {
                if (r < nrows) {
                    const ulonglong2* hs = (const ulonglong2*)h_sh[cur][r];
                    u64 ac0 = 0, ac1 = 0, ac2 = 0, ac3 = 0;
#pragma unroll
                    for (int q = 0; q < 12; q++) {
                        ulonglong2 v = hs[q];
                        if (q & 1) { fma2(ac2, v.x, whh2[2 * q]); fma2(ac3, v.y, whh2[2 * q + 1]); }
                        else        { fma2(ac0, v.x, whh2[2 * q]); fma2(ac1, v.y, whh2[2 * q + 1]); }
                    }
                    {
                        u64 tpair = *(const u64*)&h_sh[cur][r][48];
                        fma2(ac0, tpair, whh2[24]);
                    }
                    float2 f0 = up2(ac0), f1 = up2(ac1), f2 = up2(ac2), f3 = up2(ac3);
                    hg_sh[r][tid] = bias + ((f0.x + f0.y) + (f1.x + f1.y))
                                         + ((f2.x + f2.y) + (f3.x + f3.y));
                }
            }
        }
        __syncthreads();
        if (isC) {
            float gi = xg0[0] + hg_sh[r0][j0];
            float gf = xg0[1] + hg_sh[r0][50 + j0];
            float gg = xg0[2] + hg_sh[r0][100 + j0];
            float go = xg0[3] + hg_sh[r0][150 + j0];
            cc0 = sigm(gf) * cc0 + sigm(gi) * tanh_f(gg);
            float hh = sigm(go) * tanh_f(cc0);
            h_sh[cur ^ 1][r0][j0] = hh;
            int rho = rowBase + r0;
            if (dir == 0) g_F2[((size_t)u * 512 + rho) * 50 + j0] = hh;
            else          g_B2[((size_t)(511 - u) * 512 + rho) * 50 + j0] = hh;
        }
        __syncthreads();
#pragma unroll
        for (int g = 0; g < 4; g++) xg0[g] = nxg0[g];
        cur ^= 1;
    }
}

// ---------------------------------------------------------------------------
// Output linear (FFMA2): out[pos][n] = F2[pos]·wf[n] + B2[pos]·wb[n] + b[n]
// F2/B2 rows are staged through shared in 64-position tiles so the global
// loads are fully coalesced (the direct per-thread row read was 25% sector-
// efficient), then copied to registers for the dot products.
// ---------------------------------------------------------------------------
__global__ void __launch_bounds__(256) out_kernel(
    const float* __restrict__ lin_w, const float* __restrict__ lin_b,
    float* __restrict__ out)
{
    __shared__ __align__(16) float wf_sh[45 * 52];
    __shared__ __align__(16) float wb_sh[45 * 52];
    __shared__ float b_sh[45];
    __shared__ __align__(16) float stage[64][52];
    const int tid = threadIdx.x;
    for (int i = tid; i < 45 * 52; i += 256) {
        int n = i / 52, k = i - n * 52;
        wf_sh[i] = (k < 50) ? lin_w[n * 100 + k] : 0.f;
        wb_sh[i] = (k < 50) ? lin_w[n * 100 + 50 + k] : 0.f;
    }
    if (tid < 45) b_sh[tid] = lin_b[tid];
    __syncthreads();

    const int pos0 = blockIdx.x * 256;
    float acc[45];
#pragma unroll
    for (int n = 0; n < 45; n++) acc[n] = b_sh[n];

    u64 xr2[25];
    const int myTile = tid >> 6, lr = tid & 63;

    // ---- F2 phase: coalesced stage -> registers, then 45 dots ----
#pragma unroll 1
    for (int t = 0; t < 4; t++) {
        const float* src = g_F2 + (size_t)(pos0 + t * 64) * 50;
        __syncthreads();
        for (int idx = tid; idx < 3200; idx += 256) {
            int r = idx / 50, k = idx - r * 50;
            stage[r][k] = src[idx];
        }
        __syncthreads();
        if (myTile == t) {
            const u64* sp = (const u64*)stage[lr];
#pragma unroll
            for (int k = 0; k < 25; k++) xr2[k] = sp[k];
        }
    }
#pragma unroll 3
    for (int n = 0; n < 45; n++) {
        const float* w = wf_sh + n * 52;
        const ulonglong2* wv = (const ulonglong2*)w;
        u64 a = 0, b = 0;
#pragma unroll
        for (int q = 0; q < 12; q++) {
            ulonglong2 v = wv[q];
            fma2(a, xr2[2 * q], v.x);
            fma2(b, xr2[2 * q + 1], v.y);
        }
        fma2(a, xr2[24], ((const u64*)w)[24]);
        float2 fa = up2(a), fb = up2(b);
        acc[n] += (fa.x + fa.y) + (fb.x + fb.y);
    }

    // ---- B2 phase ----
#pragma unroll 1
    for (int t = 0; t < 4; t++) {
        const float* src = g_B2 + (size_t)(pos0 + t * 64) * 50;
        __syncthreads();
        for (int idx = tid; idx < 3200; idx += 256) {
            int r = idx / 50, k = idx - r * 50;
            stage[r][k] = src[idx];
        }
        __syncthreads();
        if (myTile == t) {
            const u64* sp = (const u64*)stage[lr];
#pragma unroll
            for (int k = 0; k < 25; k++) xr2[k] = sp[k];
        }
    }
#pragma unroll 3
    for (int n = 0; n < 45; n++) {
        const float* w = wb_sh + n * 52;
        const ulonglong2* wv = (const ulonglong2*)w;
        u64 a = 0, b = 0;
#pragma unroll
        for (int q = 0; q < 12; q++) {
            ulonglong2 v = wv[q];
            fma2(a, xr2[2 * q], v.x);
            fma2(b, xr2[2 * q + 1], v.y);
        }
        fma2(a, xr2[24], ((const u64*)w)[24]);
        float2 fa = up2(a), fb = up2(b);
        acc[n] += (fa.x + fa.y) + (fb.x + fb.y);
    }

    float* o = out + (size_t)(pos0 + tid) * 45;
#pragma unroll
    for (int n = 0; n < 45; n++) o[n] = acc[n];
}

// ---------------------------------------------------------------------------
extern "C" void kernel_launch(void* const* d_in, const int* in_sizes, int n_in,
                              void* d_out, int out_size) {
    const int*   x       = (const int*)  d_in[0];
    const float* emb_f1  = (const float*)d_in[1];
    const float* emb_b1  = (const float*)d_in[2];
    const float* h0_f1   = (const float*)d_in[3];
    const float* c0_f1   = (const float*)d_in[4];
    const float* Wih_f1  = (const float*)d_in[5];
    const float* Whh_f1  = (const float*)d_in[6];
    const float* bih_f1  = (const float*)d_in[7];
    const float* bhh_f1  = (const float*)d_in[8];
    const float* h0_b1   = (const float*)d_in[9];
    const float* c0_b1   = (const float*)d_in[10];
    const float* Wih_b1  = (const float*)d_in[11];
    const float* Whh_b1  = (const float*)d_in[12];
    const float* bih_b1  = (const float*)d_in[13];
    const float* bhh_b1  = (const float*)d_in[14];
    const float* h0_f2   = (const float*)d_in[15];
    const float* c0_f2   = (const float*)d_in[16];
    const float* Wih_f2  = (const float*)d_in[17];
    const float* Whh_f2  = (const float*)d_in[18];
    const float* bih_f2  = (const float*)d_in[19];
    const float* bhh_f2  = (const float*)d_in[20];
    const float* h0_b2   = (const float*)d_in[21];
    const float* c0_b2   = (const float*)d_in[22];
    const float* Wih_b2  = (const float*)d_in[23];
    const float* Whh_b2  = (const float*)d_in[24];
    const float* bih_b2  = (const float*)d_in[25];
    const float* bhh_b2  = (const float*)d_in[26];
    const float* lin_w   = (const float*)d_in[27];
    const float* lin_b   = (const float*)d_in[28];
    float* out = (float*)d_out;

    int nvocab = in_sizes[1] / 20;
    if (nvocab > 50000) nvocab = 50000;
    int tg_blocks = (nvocab + 255) / 256;

    tokgate_kernel<<<tg_blocks, 256>>>(emb_f1, Wih_f1, x, 0, nvocab);
    tokgate_kernel<<<tg_blocks, 256>>>(emb_b1, Wih_b1, x, 1, nvocab);
    r1_kernel<<<512, 128>>>(x,
                            h0_f1, c0_f1, Whh_f1, bih_f1, bhh_f1,
                            h0_b1, c0_b1, Whh_b1, bih_b1, bhh_b1);
    xg2_kernel<<<8192, 256>>>(Wih_f2, Wih_b2);
    r2_kernel<<<296, 224>>>(h0_f2, c0_f2, Whh_f2, bih_f2, bhh_f2,
                            h0_b2, c0_b2, Whh_b2, bih_b2, bhh_b2);
    out_kernel<<<1024, 256>>>(lin_w, lin_b, out);
}

// round 15
// speedup vs baseline: 1.0782x; 1.0782x over previous
#include <cuda_runtime.h>
#include <cuda_bf16.h>

// ---------------------------------------------------------------------------
// Tagger: 2-layer bidirectional LSTM (B=S=512, E=20, H1=30, H2=50, NTAGS=45)
// Reference quirk: (S,B,H)->(B,S,H) reshape with S==B is an index swap.
// Storage convention (all [time][batch][h]):
//   F1[t][b], B1[t][b]  : layer-1 hidden at time t, batch b
//   layer-2 row rho consumes at step u: ( F1[rho][u], B1[511-rho][u] )
//   F2 stored [u][rho]; B2 stored [511-u][rho]  =>  OUT reads both at [i][j].
//
// Hoisted: TG[dir][tok][j][4]   = Wih1·emb[tok]  (gate-interleaved, float4)
//          XG[dir][pos][200]    = Wih2·(F1,B1)   (gate-blocked: [i|f|g|o]x50)
// r1: 2 rows/block, 128 thr, 4 blocks/SM, shared-combine, 2 barriers (281us).
// r2: 296 blocks (2/SM), 4-or-3 rows, 224 thr, thread-per-gate (575us).
// xg2: register-tiled GEMM — 2 gate rows per thread so every x LDS.128 feeds
//      8 FFMA2 (was 4); halves the shared-read BW that bound it (L1=80%).
// ---------------------------------------------------------------------------

typedef unsigned long long u64;

__device__ float g_F1[512 * 512 * 30];
__device__ float g_B1[512 * 512 * 30];
__device__ float g_F2[512 * 512 * 50];
__device__ float g_B2[512 * 512 * 50];
__device__ float g_TGf[50000 * 120];
__device__ float g_TGb[50000 * 120];
__device__ float g_XGf[512 * 512 * 200];
__device__ float g_XGb[512 * 512 * 200];
__device__ int   g_is64;

__device__ __forceinline__ void fma2(u64 &acc, u64 a, u64 b) {
    asm("fma.rn.f32x2 %0, %1, %2, %0;" : "+l"(acc) : "l"(a), "l"(b));
}
__device__ __forceinline__ float2 up2(u64 v) {
    float2 r; asm("mov.b64 {%0, %1}, %2;" : "=f"(r.x), "=f"(r.y) : "l"(v));
    return r;
}
__device__ __forceinline__ u64 pack2(float a, float b) {
    u64 r; asm("mov.b64 %0, {%1, %2};" : "=l"(r) : "f"(a), "f"(b));
    return r;
}

__device__ __forceinline__ float sigm(float x) {
    return __fdividef(1.f, 1.f + __expf(-x));
}
__device__ __forceinline__ float tanh_f(float x) {
    float a = fabsf(x);
    float e = __expf(-2.f * a);
    float t = __fdividef(1.f - e, 1.f + e);
    return x < 0.f ? -t : t;
}

// ---------------------------------------------------------------------------
// Token gate table, BOTH dirs + dtype sniff in one launch:
//   TG[dir][tok][j*4 + g] = Wih1[dir][g*30+j] · emb[dir][tok]
// ---------------------------------------------------------------------------
__global__ void __launch_bounds__(256) tokgate_kernel(
    const float* __restrict__ emb_f, const float* __restrict__ Wih_f,
    const float* __restrict__ emb_b, const float* __restrict__ Wih_b,
    const int* __restrict__ x, int tg_blocks, int nvocab)
{
    if (blockIdx.x == 0 && threadIdx.x == 0) {
        int z = 0;
        for (int i = 1; i < 256; i += 2) z |= x[i];
        g_is64 = (z == 0) ? 1 : 0;
    }
    const int dir = (blockIdx.x >= tg_blocks) ? 1 : 0;
    const float* emb = dir ? emb_b : emb_f;
    const float* Wih = dir ? Wih_b : Wih_f;
    float* TG = dir ? g_TGb : g_TGf;

    __shared__ __align__(16) float e_sh[256][20];
    const int tid = threadIdx.x;
    const int base = (blockIdx.x - dir * tg_blocks) * 256;
    for (int idx = tid; idx < 256 * 20; idx += 256) {
        int tl = idx / 20, k = idx - tl * 20;
        int tok = base + tl;
        e_sh[tl][k] = (tok < nvocab) ? emb[tok * 20 + k] : 0.f;
    }
    __syncthreads();
    if (tid < 120) {
        const int g = tid / 30, j = tid - g * 30;
        u64 w2[10];
        const u64* wa = (const u64*)(Wih + tid * 20);
#pragma unroll
        for (int k = 0; k < 10; k++) w2[k] = wa[k];
        int nmax = nvocab - base; if (nmax > 256) nmax = 256;
        for (int tl = 0; tl < nmax; tl++) {
            const ulonglong2* xs = (const ulonglong2*)e_sh[tl];
            u64 ac0 = 0, ac1 = 0, ac2 = 0, ac3 = 0;
#pragma unroll
            for (int q = 0; q < 5; q++) {
                ulonglong2 v = xs[q];
                if (q & 1) { fma2(ac2, v.x, w2[2 * q]); fma2(ac3, v.y, w2[2 * q + 1]); }
                else        { fma2(ac0, v.x, w2[2 * q]); fma2(ac1, v.y, w2[2 * q + 1]); }
            }
            float2 f0 = up2(ac0), f1 = up2(ac1), f2 = up2(ac2), f3 = up2(ac3);
            TG[(base + tl) * 120 + j * 4 + g] = ((f0.x + f0.y) + (f1.x + f1.y))
                                              + ((f2.x + f2.y) + (f3.x + f3.y));
        }
    }
}

// ---------------------------------------------------------------------------
// Layer 1 scan: 512 blocks (2 dirs x 256), 2 batch rows/block, 128 threads,
// 4 blocks/SM, shared-combine, 2 barriers.
// ---------------------------------------------------------------------------
__global__ void __launch_bounds__(128, 4) r1_kernel(
    const int* __restrict__ x,
    const float* __restrict__ h0f, const float* __restrict__ c0f,
    const float* __restrict__ Whhf,
    const float* __restrict__ bihf, const float* __restrict__ bhhf,
    const float* __restrict__ h0b, const float* __restrict__ c0b,
    const float* __restrict__ Whhb,
    const float* __restrict__ bihb, const float* __restrict__ bhhb)
{
    const int dir = blockIdx.x >> 8;           // 0 = forward, 1 = backward
    const int rowBase = (blockIdx.x & 255) * 2;
    const float* Whh = dir ? Whhb : Whhf;
    const float* bih = dir ? bihb : bihf;
    const float* bhh = dir ? bhhb : bhhf;
    const float* h0  = dir ? h0b  : h0f;
    const float* c0  = dir ? c0b  : c0f;
    const float* TG  = dir ? g_TGb : g_TGf;
    float* outp = dir ? g_B1 : g_F1;

    const int tid = threadIdx.x;
    __shared__ __align__(16) float h_sh[2][2][32];
    __shared__ float hg_sh[2][120];

    const bool isH = (tid < 120);
    u64 whh2[15];
    float bias = 0.f;
    if (isH) {
        const u64* wb = (const u64*)(Whh + tid * 30);   // 120B rows, 8B-aligned
#pragma unroll
        for (int k = 0; k < 15; k++) whh2[k] = wb[k];
        bias = bih[tid] + bhh[tid];
    }
    for (int idx = tid; idx < 2 * 32; idx += 128) {
        int r = idx >> 5, k = idx & 31;
        h_sh[0][r][k] = (k < 30) ? h0[(rowBase + r) * 30 + k] : 0.f;
        h_sh[1][r][k] = 0.f;
    }
    // combine: task m = tid in [0,60): r = m/30, j = m%30
    const int r0 = tid / 30, j0 = tid - r0 * 30;
    const bool isC = (tid < 60);
    const int row0 = rowBase + r0;
    const int is64 = g_is64;
    float cc0 = isC ? c0[row0 * 30 + j0] : 0.f;

    // prefetch token gates for step 0 (one float4, gate-interleaved TG)
    float4 tg = make_float4(0.f, 0.f, 0.f, 0.f);
    if (isC) {
        int t0 = dir ? 511 : 0;
        int i0 = row0 * 512 + t0;
        int tok = x[is64 ? 2 * i0 : i0];
        tg = *(const float4*)&TG[tok * 120 + j0 * 4];
    }
    __syncthreads();

    int cur = 0;
    for (int s = 0; s < 512; s++) {
        const int t = dir ? (511 - s) : s;
        float4 ntg = make_float4(0.f, 0.f, 0.f, 0.f);
        if (s < 511 && isC) {
            int tn = dir ? (510 - s) : (s + 1);
            int in = row0 * 512 + tn;
            int tok = x[is64 ? 2 * in : in];
            ntg = *(const float4*)&TG[tok * 120 + j0 * 4];
        }
        if (isH) {
#pragma unroll
            for (int r = 0; r < 2; r++) {
                const ulonglong2* hs = (const ulonglong2*)h_sh[cur][r];
                u64 ac0 = 0, ac1 = 0, ac2 = 0, ac3 = 0;
#pragma unroll
                for (int q = 0; q < 7; q++) {
                    ulonglong2 v = hs[q];
                    if (q & 1) { fma2(ac2, v.x, whh2[2 * q]); fma2(ac3, v.y, whh2[2 * q + 1]); }
                    else        { fma2(ac0, v.x, whh2[2 * q]); fma2(ac1, v.y, whh2[2 * q + 1]); }
                }
                {
                    u64 tpair = *(const u64*)&h_sh[cur][r][28];
                    fma2(ac2, tpair, whh2[14]);
                }
                float2 f0 = up2(ac0), f1 = up2(ac1), f2 = up2(ac2), f3 = up2(ac3);
                hg_sh[r][tid] = bias + ((f0.x + f0.y) + (f1.x + f1.y))
                                     + ((f2.x + f2.y) + (f3.x + f3.y));
            }
        }
        __syncthreads();
        if (isC) {
            float gi = tg.x + hg_sh[r0][j0];
            float gf = tg.y + hg_sh[r0][30 + j0];
            float gg = tg.z + hg_sh[r0][60 + j0];
            float go = tg.w + hg_sh[r0][90 + j0];
            cc0 = sigm(gf) * cc0 + sigm(gi) * tanh_f(gg);
            float hh = sigm(go) * tanh_f(cc0);
            h_sh[cur ^ 1][r0][j0] = hh;
            outp[((size_t)t * 512 + row0) * 30 + j0] = hh;
        }
        __syncthreads();
        tg = ntg;
        cur ^= 1;
    }
}

// ---------------------------------------------------------------------------
// Layer-2 input gates, register-tiled: thread j (j<100) computes gate rows
// j and j+100. Each x LDS.128 feeds 8 FFMA2 -> shared-read BW halved.
// grid = 8192: dir = bx>>12, rho = (bx&4095)>>3, u-chunk = (bx&7)*64.
// Output staged through shared for fully coalesced 200-float row stores.
// ---------------------------------------------------------------------------
__global__ void __launch_bounds__(128, 3) xg2_kernel(
    const float* __restrict__ Wihf, const float* __restrict__ Wihb)
{
    const int bx = blockIdx.x;
    const int dir = bx >> 12;
    const int rem = bx & 4095;
    const int rho = rem >> 3;
    const int u0  = (rem & 7) * 64;
    const float* Wih = dir ? Wihb : Wihf;
    float* XG = dir ? g_XGb : g_XGf;

    __shared__ __align__(16) float x_sh[64][60];
    __shared__ __align__(16) float stage_sh[16][200];
    const int tid = threadIdx.x;
    const float* f1 = g_F1 + ((size_t)rho * 512 + u0) * 30;
    const float* b1 = g_B1 + ((size_t)(511 - rho) * 512 + u0) * 30;
    for (int idx = tid; idx < 1920; idx += 128) {
        int r = idx / 30, k = idx - r * 30;
        x_sh[r][k]      = f1[idx];
        x_sh[r][30 + k] = b1[idx];
    }

    const bool isW = (tid < 100);
    u64 wA[30], wB[30];
    if (isW) {
        const u64* wa = (const u64*)(Wih + tid * 60);
        const u64* wb = (const u64*)(Wih + (tid + 100) * 60);
#pragma unroll
        for (int k = 0; k < 30; k++) { wA[k] = wa[k]; wB[k] = wb[k]; }
    }
    __syncthreads();

    float* outbase = XG + ((size_t)rho * 512 + u0) * 200;
#pragma unroll 1
    for (int c = 0; c < 4; c++) {
        if (isW) {
#pragma unroll 2
            for (int p = 0; p < 16; p++) {
                const ulonglong2* xs = (const ulonglong2*)x_sh[c * 16 + p];
                u64 a0 = 0, a1 = 0, a2 = 0, a3 = 0;
                u64 b0 = 0, b1v = 0, b2 = 0, b3 = 0;
#pragma unroll
                for (int q = 0; q < 15; q++) {
                    ulonglong2 v = xs[q];
                    if (q & 1) {
                        fma2(a2, v.x, wA[2 * q]); fma2(a3, v.y, wA[2 * q + 1]);
                        fma2(b2, v.x, wB[2 * q]); fma2(b3, v.y, wB[2 * q + 1]);
                    } else {
                        fma2(a0, v.x, wA[2 * q]); fma2(a1, v.y, wA[2 * q + 1]);
                        fma2(b0, v.x, wB[2 * q]); fma2(b1v, v.y, wB[2 * q + 1]);
                    }
                }
                float2 fa0 = up2(a0), fa1 = up2(a1), fa2 = up2(a2), fa3 = up2(a3);
                float2 fb0 = up2(b0), fb1 = up2(b1v), fb2 = up2(b2), fb3 = up2(b3);
                stage_sh[p][tid] = ((fa0.x + fa0.y) + (fa1.x + fa1.y))
                                 + ((fa2.x + fa2.y) + (fa3.x + fa3.y));
                stage_sh[p][tid + 100] = ((fb0.x + fb0.y) + (fb1.x + fb1.y))
                                       + ((fb2.x + fb2.y) + (fb3.x + fb3.y));
            }
        }
        __syncthreads();
        float* ob = outbase + (size_t)(c * 16) * 200;
        for (int idx = tid; idx < 3200; idx += 128) {
            ob[idx] = ((const float*)stage_sh)[idx];
        }
        __syncthreads();
    }
}

// ---------------------------------------------------------------------------
// Layer 2 scan (round-12 proven config): 296 blocks (2 dirs x 148 = 2/SM),
// 4-or-3 rows/block, 224 threads, thread-per-gate.
// ---------------------------------------------------------------------------
__global__ void __launch_bounds__(224, 2) r2_kernel(
    const float* __restrict__ h0f, const float* __restrict__ c0f,
    const float* __restrict__ Whhf,
    const float* __restrict__ bihf, const float* __restrict__ bhhf,
    const float* __restrict__ h0b, const float* __restrict__ c0b,
    const float* __restrict__ Whhb,
    const float* __restrict__ bihb, const float* __restrict__ bhhb)
{
    const int dir = (blockIdx.x >= 148) ? 1 : 0;
    const int b   = blockIdx.x - dir * 148;
    const int rowBase = 3 * b + (b < 68 ? b : 68);
    const int nrows   = (b < 68) ? 4 : 3;
    const float* Whh = dir ? Whhb : Whhf;
    const float* bih = dir ? bihb : bihf;
    const float* bhh = dir ? bhhb : bhhf;
    const float* h0  = dir ? h0b  : h0f;
    const float* c0  = dir ? c0b  : c0f;
    const float* XG  = dir ? g_XGb : g_XGf;

    const int tid = threadIdx.x;
    __shared__ __align__(16) float h_sh[2][4][52];
    __shared__ float hg_sh[4][200];

    const bool isH = (tid < 200);
    u64 whh2[25];
    float bias = 0.f;
    if (isH) {
        const u64* wb = (const u64*)(Whh + tid * 50);   // 200B rows, 8B-aligned
#pragma unroll
        for (int k = 0; k < 25; k++) whh2[k] = wb[k];
        bias = bih[tid] + bhh[tid];
    }
    for (int idx = tid; idx < 4 * 52; idx += 224) {
        int r = idx / 52, k = idx - r * 52;
        h_sh[0][r][k] = (r < nrows && k < 50) ? h0[(rowBase + r) * 50 + k] : 0.f;
        h_sh[1][r][k] = 0.f;
    }
    // combine: task m = tid in [0,200): r = m/50, j = m%50
    const int r0 = tid / 50, j0 = tid - r0 * 50;
    const bool isC = (tid < 200) && (r0 < nrows);
    float cc0 = isC ? c0[(rowBase + r0) * 50 + j0] : 0.f;
    const size_t xb0 = isC ? ((size_t)(rowBase + r0) * 512) * 200 + j0 : 0;

    // prefetch XG for step 0
    float xg0[4] = {0,0,0,0};
    if (isC) {
        int u0 = dir ? 511 : 0;
#pragma unroll
        for (int g = 0; g < 4; g++) xg0[g] = XG[xb0 + (size_t)u0 * 200 + g * 50];
    }
    __syncthreads();

    int cur = 0;
    for (int s = 0; s < 512; s++) {
        const int u = dir ? (511 - s) : s;
        float nxg0[4] = {0,0,0,0};
        if (s < 511 && isC) {
            int un = dir ? (510 - s) : (s + 1);
#pragma unroll
            for (int g = 0; g < 4; g++) nxg0[g] = XG[xb0 + (size_t)un * 200 + g * 50];
        }
        if (isH) {
#pragma unroll
            for (int r = 0; r < 4; r++) {
                if (r < nrows) {
                    const ulonglong2* hs = (const ulonglong2*)h_sh[cur][r];
                    u64 ac0 = 0, ac1 = 0, ac2 = 0, ac3 = 0;
#pragma unroll
                    for (int q = 0; q < 12; q++) {
                        ulonglong2 v = hs[q];
                        if (q & 1) { fma2(ac2, v.x, whh2[2 * q]); fma2(ac3, v.y, whh2[2 * q + 1]); }
                        else        { fma2(ac0, v.x, whh2[2 * q]); fma2(ac1, v.y, whh2[2 * q + 1]); }
                    }
                    {
                        u64 tpair = *(const u64*)&h_sh[cur][r][48];
                        fma2(ac0, tpair, whh2[24]);
                    }
                    float2 f0 = up2(ac0), f1 = up2(ac1), f2 = up2(ac2), f3 = up2(ac3);
                    hg_sh[r][tid] = bias + ((f0.x + f0.y) + (f1.x + f1.y))
                                         + ((f2.x + f2.y) + (f3.x + f3.y));
                }
            }
        }
        __syncthreads();
        if (isC) {
            float gi = xg0[0] + hg_sh[r0][j0];
            float gf = xg0[1] + hg_sh[r0][50 + j0];
            float gg = xg0[2] + hg_sh[r0][100 + j0];
            float go = xg0[3] + hg_sh[r0][150 + j0];
            cc0 = sigm(gf) * cc0 + sigm(gi) * tanh_f(gg);
            float hh = sigm(go) * tanh_f(cc0);
            h_sh[cur ^ 1][r0][j0] = hh;
            int rho = rowBase + r0;
            if (dir == 0) g_F2[((size_t)u * 512 + rho) * 50 + j0] = hh;
            else          g_B2[((size_t)(511 - u) * 512 + rho) * 50 + j0] = hh;
        }
        __syncthreads();
#pragma unroll
        for (int g = 0; g < 4; g++) xg0[g] = nxg0[g];
        cur ^= 1;
    }
}

// ---------------------------------------------------------------------------
// Output linear (FFMA2): out[pos][n] = F2[pos]·wf[n] + B2[pos]·wb[n] + b[n]
// ---------------------------------------------------------------------------
__global__ void __launch_bounds__(256) out_kernel(
    const float* __restrict__ lin_w, const float* __restrict__ lin_b,
    float* __restrict__ out)
{
    __shared__ __align__(16) float wf_sh[45 * 52];
    __shared__ __align__(16) float wb_sh[45 * 52];
    __shared__ float b_sh[45];
    const int tid = threadIdx.x;
    for (int i = tid; i < 45 * 52; i += 256) {
        int n = i / 52, k = i - n * 52;
        wf_sh[i] = (k < 50) ? lin_w[n * 100 + k] : 0.f;
        wb_sh[i] = (k < 50) ? lin_w[n * 100 + 50 + k] : 0.f;
    }
    if (tid < 45) b_sh[tid] = lin_b[tid];
    __syncthreads();

    const int pos = blockIdx.x * 256 + tid;
    float acc[45];
#pragma unroll
    for (int n = 0; n < 45; n++) acc[n] = b_sh[n];

    {
        const u64* xp = (const u64*)(g_F2 + (size_t)pos * 50);
        u64 xr2[25];
#pragma unroll
        for (int k = 0; k < 25; k++) xr2[k] = xp[k];
#pragma unroll 3
        for (int n = 0; n < 45; n++) {
            const float* w = wf_sh + n * 52;
            const ulonglong2* wv = (const ulonglong2*)w;
            u64 a = 0, b = 0;
#pragma unroll
            for (int q = 0; q < 12; q++) {
                ulonglong2 v = wv[q];
                fma2(a, xr2[2 * q], v.x);
                fma2(b, xr2[2 * q + 1], v.y);
            }
            fma2(a, xr2[24], ((const u64*)w)[24]);
            float2 fa = up2(a), fb = up2(b);
            acc[n] += (fa.x + fa.y) + (fb.x + fb.y);
        }
    }
    {
        const u64* xp = (const u64*)(g_B2 + (size_t)pos * 50);
        u64 xr2[25];
#pragma unroll
        for (int k = 0; k < 25; k++) xr2[k] = xp[k];
#pragma unroll 3
        for (int n = 0; n < 45; n++) {
            const float* w = wb_sh + n * 52;
            const ulonglong2* wv = (const ulonglong2*)w;
            u64 a = 0, b = 0;
#pragma unroll
            for (int q = 0; q < 12; q++) {
                ulonglong2 v = wv[q];
                fma2(a, xr2[2 * q], v.x);
                fma2(b, xr2[2 * q + 1], v.y);
            }
            fma2(a, xr2[24], ((const u64*)w)[24]);
            float2 fa = up2(a), fb = up2(b);
            acc[n] += (fa.x + fa.y) + (fb.x + fb.y);
        }
    }
    float* o = out + (size_t)pos * 45;
#pragma unroll
    for (int n = 0; n < 45; n++) o[n] = acc[n];
}

// ---------------------------------------------------------------------------
extern "C" void kernel_launch(void* const* d_in, const int* in_sizes, int n_in,
                              void* d_out, int out_size) {
    const int*   x       = (const int*)  d_in[0];
    const float* emb_f1  = (const float*)d_in[1];
    const float* emb_b1  = (const float*)d_in[2];
    const float* h0_f1   = (const float*)d_in[3];
    const float* c0_f1   = (const float*)d_in[4];
    const float* Wih_f1  = (const float*)d_in[5];
    const float* Whh_f1  = (const float*)d_in[6];
    const float* bih_f1  = (const float*)d_in[7];
    const float* bhh_f1  = (const float*)d_in[8];
    const float* h0_b1   = (const float*)d_in[9];
    const float* c0_b1   = (const float*)d_in[10];
    const float* Wih_b1  = (const float*)d_in[11];
    const float* Whh_b1  = (const float*)d_in[12];
    const float* bih_b1  = (const float*)d_in[13];
    const float* bhh_b1  = (const float*)d_in[14];
    const float* h0_f2   = (const float*)d_in[15];
    const float* c0_f2   = (const float*)d_in[16];
    const float* Wih_f2  = (const float*)d_in[17];
    const float* Whh_f2  = (const float*)d_in[18];
    const float* bih_f2  = (const float*)d_in[19];
    const float* bhh_f2  = (const float*)d_in[20];
    const float* h0_b2   = (const float*)d_in[21];
    const float* c0_b2   = (const float*)d_in[22];
    const float* Wih_b2  = (const float*)d_in[23];
    const float* Whh_b2  = (const float*)d_in[24];
    const float* bih_b2  = (const float*)d_in[25];
    const float* bhh_b2  = (const float*)d_in[26];
    const float* lin_w   = (const float*)d_in[27];
    const float* lin_b   = (const float*)d_in[28];
    float* out = (float*)d_out;

    int nvocab = in_sizes[1] / 20;
    if (nvocab > 50000) nvocab = 50000;
    int tg_blocks = (nvocab + 255) / 256;

    tokgate_kernel<<<2 * tg_blocks, 256>>>(emb_f1, Wih_f1, emb_b1, Wih_b1,
                                           x, tg_blocks, nvocab);
    r1_kernel<<<512, 128>>>(x,
                            h0_f1, c0_f1, Whh_f1, bih_f1, bhh_f1,
                            h0_b1, c0_b1, Whh_b1, bih_b1, bhh_b1);
    xg2_kernel<<<8192, 128>>>(Wih_f2, Wih_b2);
    r2_kernel<<<296, 224>>>(h0_f2, c0_f2, Whh_f2, bih_f2, bhh_f2,
                            h0_b2, c0_b2, Whh_b2, bih_b2, bhh_b2);
    out_kernel<<<1024, 256>>>(lin_w, lin_b, out);
}

// round 16
// speedup vs baseline: 1.1195x; 1.0383x over previous
#include <cuda_runtime.h>
#include <cuda_bf16.h>

// ---------------------------------------------------------------------------
// Tagger: 2-layer bidirectional LSTM (B=S=512, E=20, H1=30, H2=50, NTAGS=45)
// Reference quirk: (S,B,H)->(B,S,H) reshape with S==B is an index swap.
// Storage convention (all [time][batch][h]):
//   F1[t][b], B1[t][b]  : layer-1 hidden at time t, batch b
//   layer-2 row rho consumes at step u: ( F1[rho][u], B1[511-rho][u] )
//   F2 stored [u][rho]; B2 stored [511-u][rho]  =>  OUT reads both at [i][j].
//
// Hoisted: TG[dir][tok][j][4]   = Wih1·emb[tok]  (gate-interleaved, float4)
//          XG[dir][pos][200]    = Wih2·(F1,B1)   (gate-blocked: [i|f|g|o]x50)
// r1: 2 rows/block, 128 thr, 4 blocks/SM, shared-combine, 2 barriers (281us).
// r2: 296 blocks (2/SM), 4-or-3 rows, 224 thr, thread-per-gate (575us).
// xg2: G=2 register-tiled, 128 pos/block, full x-row batched into registers
//      per position, DIRECT coalesced stores (no staging, 1 barrier total).
// ---------------------------------------------------------------------------

typedef unsigned long long u64;

__device__ float g_F1[512 * 512 * 30];
__device__ float g_B1[512 * 512 * 30];
__device__ float g_F2[512 * 512 * 50];
__device__ float g_B2[512 * 512 * 50];
__device__ float g_TGf[50000 * 120];
__device__ float g_TGb[50000 * 120];
__device__ float g_XGf[512 * 512 * 200];
__device__ float g_XGb[512 * 512 * 200];
__device__ int   g_is64;

__device__ __forceinline__ void fma2(u64 &acc, u64 a, u64 b) {
    asm("fma.rn.f32x2 %0, %1, %2, %0;" : "+l"(acc) : "l"(a), "l"(b));
}
__device__ __forceinline__ float2 up2(u64 v) {
    float2 r; asm("mov.b64 {%0, %1}, %2;" : "=f"(r.x), "=f"(r.y) : "l"(v));
    return r;
}
__device__ __forceinline__ u64 pack2(float a, float b) {
    u64 r; asm("mov.b64 %0, {%1, %2};" : "=l"(r) : "f"(a), "f"(b));
    return r;
}

__device__ __forceinline__ float sigm(float x) {
    return __fdividef(1.f, 1.f + __expf(-x));
}
__device__ __forceinline__ float tanh_f(float x) {
    float a = fabsf(x);
    float e = __expf(-2.f * a);
    float t = __fdividef(1.f - e, 1.f + e);
    return x < 0.f ? -t : t;
}

// ---------------------------------------------------------------------------
// Dtype sniff: x may be int32 or int64 (odd words all zero => int64).
// ---------------------------------------------------------------------------
__global__ void sniff_kernel(const int* __restrict__ xr) {
    int z = 0;
    for (int i = 1; i < 256; i += 2) z |= xr[i];
    g_is64 = (z == 0) ? 1 : 0;
}

// ---------------------------------------------------------------------------
// Token gate table, BOTH dirs in one launch:
//   TG[dir][tok][j*4 + g] = Wih1[dir][g*30+j] · emb[dir][tok]
// ---------------------------------------------------------------------------
__global__ void __launch_bounds__(256) tokgate_kernel(
    const float* __restrict__ emb_f, const float* __restrict__ Wih_f,
    const float* __restrict__ emb_b, const float* __restrict__ Wih_b,
    int tg_blocks, int nvocab)
{
    const int dir = (blockIdx.x >= tg_blocks) ? 1 : 0;
    const float* emb = dir ? emb_b : emb_f;
    const float* Wih = dir ? Wih_b : Wih_f;
    float* TG = dir ? g_TGb : g_TGf;

    __shared__ __align__(16) float e_sh[256][20];
    const int tid = threadIdx.x;
    const int base = (blockIdx.x - dir * tg_blocks) * 256;
    for (int idx = tid; idx < 256 * 20; idx += 256) {
        int tl = idx / 20, k = idx - tl * 20;
        int tok = base + tl;
        e_sh[tl][k] = (tok < nvocab) ? emb[tok * 20 + k] : 0.f;
    }
    __syncthreads();
    if (tid < 120) {
        const int g = tid / 30, j = tid - g * 30;
        u64 w2[10];
        const u64* wa = (const u64*)(Wih + tid * 20);
#pragma unroll
        for (int k = 0; k < 10; k++) w2[k] = wa[k];
        int nmax = nvocab - base; if (nmax > 256) nmax = 256;
        for (int tl = 0; tl < nmax; tl++) {
            const ulonglong2* xs = (const ulonglong2*)e_sh[tl];
            u64 ac0 = 0, ac1 = 0, ac2 = 0, ac3 = 0;
#pragma unroll
            for (int q = 0; q < 5; q++) {
                ulonglong2 v = xs[q];
                if (q & 1) { fma2(ac2, v.x, w2[2 * q]); fma2(ac3, v.y, w2[2 * q + 1]); }
                else        { fma2(ac0, v.x, w2[2 * q]); fma2(ac1, v.y, w2[2 * q + 1]); }
            }
            float2 f0 = up2(ac0), f1 = up2(ac1), f2 = up2(ac2), f3 = up2(ac3);
            TG[(base + tl) * 120 + j * 4 + g] = ((f0.x + f0.y) + (f1.x + f1.y))
                                              + ((f2.x + f2.y) + (f3.x + f3.y));
        }
    }
}

// ---------------------------------------------------------------------------
// Layer 1 scan: 512 blocks (2 dirs x 256), 2 batch rows/block, 128 threads,
// 4 blocks/SM, shared-combine, 2 barriers.
// ---------------------------------------------------------------------------
__global__ void __launch_bounds__(128, 4) r1_kernel(
    const int* __restrict__ x,
    const float* __restrict__ h0f, const float* __restrict__ c0f,
    const float* __restrict__ Whhf,
    const float* __restrict__ bihf, const float* __restrict__ bhhf,
    const float* __restrict__ h0b, const float* __restrict__ c0b,
    const float* __restrict__ Whhb,
    const float* __restrict__ bihb, const float* __restrict__ bhhb)
{
    const int dir = blockIdx.x >> 8;           // 0 = forward, 1 = backward
    const int rowBase = (blockIdx.x & 255) * 2;
    const float* Whh = dir ? Whhb : Whhf;
    const float* bih = dir ? bihb : bihf;
    const float* bhh = dir ? bhhb : bhhf;
    const float* h0  = dir ? h0b  : h0f;
    const float* c0  = dir ? c0b  : c0f;
    const float* TG  = dir ? g_TGb : g_TGf;
    float* outp = dir ? g_B1 : g_F1;

    const int tid = threadIdx.x;
    __shared__ __align__(16) float h_sh[2][2][32];
    __shared__ float hg_sh[2][120];

    const bool isH = (tid < 120);
    u64 whh2[15];
    float bias = 0.f;
    if (isH) {
        const u64* wb = (const u64*)(Whh + tid * 30);   // 120B rows, 8B-aligned
#pragma unroll
        for (int k = 0; k < 15; k++) whh2[k] = wb[k];
        bias = bih[tid] + bhh[tid];
    }
    for (int idx = tid; idx < 2 * 32; idx += 128) {
        int r = idx >> 5, k = idx & 31;
        h_sh[0][r][k] = (k < 30) ? h0[(rowBase + r) * 30 + k] : 0.f;
        h_sh[1][r][k] = 0.f;
    }
    // combine: task m = tid in [0,60): r = m/30, j = m%30
    const int r0 = tid / 30, j0 = tid - r0 * 30;
    const bool isC = (tid < 60);
    const int row0 = rowBase + r0;
    const int is64 = g_is64;
    float cc0 = isC ? c0[row0 * 30 + j0] : 0.f;

    // prefetch token gates for step 0 (one float4, gate-interleaved TG)
    float4 tg = make_float4(0.f, 0.f, 0.f, 0.f);
    if (isC) {
        int t0 = dir ? 511 : 0;
        int i0 = row0 * 512 + t0;
        int tok = x[is64 ? 2 * i0 : i0];
        tg = *(const float4*)&TG[tok * 120 + j0 * 4];
    }
    __syncthreads();

    int cur = 0;
    for (int s = 0; s < 512; s++) {
        const int t = dir ? (511 - s) : s;
        float4 ntg = make_float4(0.f, 0.f, 0.f, 0.f);
        if (s < 511 && isC) {
            int tn = dir ? (510 - s) : (s + 1);
            int in = row0 * 512 + tn;
            int tok = x[is64 ? 2 * in : in];
            ntg = *(const float4*)&TG[tok * 120 + j0 * 4];
        }
        if (isH) {
#pragma unroll
            for (int r = 0; r < 2; r++) {
                const ulonglong2* hs = (const ulonglong2*)h_sh[cur][r];
                u64 ac0 = 0, ac1 = 0, ac2 = 0, ac3 = 0;
#pragma unroll
                for (int q = 0; q < 7; q++) {
                    ulonglong2 v = hs[q];
                    if (q & 1) { fma2(ac2, v.x, whh2[2 * q]); fma2(ac3, v.y, whh2[2 * q + 1]); }
                    else        { fma2(ac0, v.x, whh2[2 * q]); fma2(ac1, v.y, whh2[2 * q + 1]); }
                }
                {
                    u64 tpair = *(const u64*)&h_sh[cur][r][28];
                    fma2(ac2, tpair, whh2[14]);
                }
                float2 f0 = up2(ac0), f1 = up2(ac1), f2 = up2(ac2), f3 = up2(ac3);
                hg_sh[r][tid] = bias + ((f0.x + f0.y) + (f1.x + f1.y))
                                     + ((f2.x + f2.y) + (f3.x + f3.y));
            }
        }
        __syncthreads();
        if (isC) {
            float gi = tg.x + hg_sh[r0][j0];
            float gf = tg.y + hg_sh[r0][30 + j0];
            float gg = tg.z + hg_sh[r0][60 + j0];
            float go = tg.w + hg_sh[r0][90 + j0];
            cc0 = sigm(gf) * cc0 + sigm(gi) * tanh_f(gg);
            float hh = sigm(go) * tanh_f(cc0);
            h_sh[cur ^ 1][r0][j0] = hh;
            outp[((size_t)t * 512 + row0) * 30 + j0] = hh;
        }
        __syncthreads();
        tg = ntg;
        cur ^= 1;
    }
}

// ---------------------------------------------------------------------------
// Layer-2 input gates, G=2 register-tiled, 128 positions/block:
//   thread j (j<100) computes gate rows j and j+100 for 128 positions.
// Full 240B x-row batched into registers per position (15 LDS.128 in flight),
// stores are direct and coalesced (consecutive tid -> consecutive addresses).
// grid = 4096: dir = bx>>11, rho = (bx&2047)>>2, u-chunk = (bx&3)*128
// ---------------------------------------------------------------------------
__global__ void __launch_bounds__(128, 2) xg2_kernel(
    const float* __restrict__ Wihf, const float* __restrict__ Wihb)
{
    const int bx = blockIdx.x;
    const int dir = bx >> 11;
    const int rem = bx & 2047;
    const int rho = rem >> 2;
    const int u0  = (rem & 3) * 128;
    const float* Wih = dir ? Wihb : Wihf;
    float* XG = dir ? g_XGb : g_XGf;

    __shared__ __align__(16) float x_sh[128][60];
    const int tid = threadIdx.x;
    const size_t pos0 = (size_t)rho * 512 + u0;
    const float* f1 = g_F1 + pos0 * 30;
    const float* b1 = g_B1 + ((size_t)(511 - rho) * 512 + u0) * 30;
    for (int idx = tid; idx < 128 * 30; idx += 128) {
        int r = idx / 30, k = idx - r * 30;
        x_sh[r][k]      = f1[idx];
        x_sh[r][30 + k] = b1[idx];
    }

    const bool isW = (tid < 100);
    u64 wA[30], wB[30];
    if (isW) {
        const u64* wa = (const u64*)(Wih + tid * 60);
        const u64* wb = (const u64*)(Wih + (tid + 100) * 60);
#pragma unroll
        for (int k = 0; k < 30; k++) { wA[k] = wa[k]; wB[k] = wb[k]; }
    }
    __syncthreads();

    if (isW) {
        float* ob = XG + pos0 * 200 + tid;
#pragma unroll 2
        for (int p = 0; p < 128; p++) {
            // batch the whole x row into registers first: 15 LDS.128 in flight
            ulonglong2 xv[15];
            const ulonglong2* xs = (const ulonglong2*)x_sh[p];
#pragma unroll
            for (int q = 0; q < 15; q++) xv[q] = xs[q];

            u64 a0 = 0, a1 = 0, a2 = 0, a3 = 0;
            u64 b0 = 0, b1v = 0, b2 = 0, b3 = 0;
#pragma unroll
            for (int q = 0; q < 15; q++) {
                if (q & 1) {
                    fma2(a2, xv[q].x, wA[2 * q]); fma2(a3, xv[q].y, wA[2 * q + 1]);
                    fma2(b2, xv[q].x, wB[2 * q]); fma2(b3, xv[q].y, wB[2 * q + 1]);
                } else {
                    fma2(a0, xv[q].x, wA[2 * q]); fma2(a1, xv[q].y, wA[2 * q + 1]);
                    fma2(b0, xv[q].x, wB[2 * q]); fma2(b1v, xv[q].y, wB[2 * q + 1]);
                }
            }
            float2 fa0 = up2(a0), fa1 = up2(a1), fa2 = up2(a2), fa3 = up2(a3);
            float2 fb0 = up2(b0), fb1 = up2(b1v), fb2 = up2(b2), fb3 = up2(b3);
            ob[p * 200]       = ((fa0.x + fa0.y) + (fa1.x + fa1.y))
                              + ((fa2.x + fa2.y) + (fa3.x + fa3.y));
            ob[p * 200 + 100] = ((fb0.x + fb0.y) + (fb1.x + fb1.y))
                              + ((fb2.x + fb2.y) + (fb3.x + fb3.y));
        }
    }
}

// ---------------------------------------------------------------------------
// Layer 2 scan (round-12 proven config): 296 blocks (2 dirs x 148 = 2/SM),
// 4-or-3 rows/block, 224 threads, thread-per-gate.
// ---------------------------------------------------------------------------
__global__ void __launch_bounds__(224, 2) r2_kernel(
    const float* __restrict__ h0f, const float* __restrict__ c0f,
    const float* __restrict__ Whhf,
    const float* __restrict__ bihf, const float* __restrict__ bhhf,
    const float* __restrict__ h0b, const float* __restrict__ c0b,
    const float* __restrict__ Whhb,
    const float* __restrict__ bihb, const float* __restrict__ bhhb)
{
    const int dir = (blockIdx.x >= 148) ? 1 : 0;
    const int b   = blockIdx.x - dir * 148;
    const int rowBase = 3 * b + (b < 68 ? b : 68);
    const int nrows   = (b < 68) ? 4 : 3;
    const float* Whh = dir ? Whhb : Whhf;
    const float* bih = dir ? bihb : bihf;
    const float* bhh = dir ? bhhb : bhhf;
    const float* h0  = dir ? h0b  : h0f;
    const float* c0  = dir ? c0b  : c0f;
    const float* XG  = dir ? g_XGb : g_XGf;

    const int tid = threadIdx.x;
    __shared__ __align__(16) float h_sh[2][4][52];
    __shared__ float hg_sh[4][200];

    const bool isH = (tid < 200);
    u64 whh2[25];
    float bias = 0.f;
    if (isH) {
        const u64* wb = (const u64*)(Whh + tid * 50);   // 200B rows, 8B-aligned
#pragma unroll
        for (int k = 0; k < 25; k++) whh2[k] = wb[k];
        bias = bih[tid] + bhh[tid];
    }
    for (int idx = tid; idx < 4 * 52; idx += 224) {
        int r = idx / 52, k = idx - r * 52;
        h_sh[0][r][k] = (r < nrows && k < 50) ? h0[(rowBase + r) * 50 + k] : 0.f;
        h_sh[1][r][k] = 0.f;
    }
    // combine: task m = tid in [0,200): r = m/50, j = m%50
    const int r0 = tid / 50, j0 = tid - r0 * 50;
    const bool isC = (tid < 200) && (r0 < nrows);
    float cc0 = isC ? c0[(rowBase + r0) * 50 + j0] : 0.f;
    const size_t xb0 = isC ? ((size_t)(rowBase + r0) * 512) * 200 + j0 : 0;

    // prefetch XG for step 0
    float xg0[4] = {0,0,0,0};
    if (isC) {
        int u0 = dir ? 511 : 0;
#pragma unroll
        for (int g = 0; g < 4; g++) xg0[g] = XG[xb0 + (size_t)u0 * 200 + g * 50];
    }
    __syncthreads();

    int cur = 0;
    for (int s = 0; s < 512; s++) {
        const int u = dir ? (511 - s) : s;
        float nxg0[4] = {0,0,0,0};
        if (s < 511 && isC) {
            int un = dir ? (510 - s) : (s + 1);
#pragma unroll
            for (int g = 0; g < 4; g++) nxg0[g] = XG[xb0 + (size_t)un * 200 + g * 50];
        }
        if (isH) {
#pragma unroll
            for (int r = 0; r < 4; r++) {
                if (r < nrows) {
                    const ulonglong2* hs = (const ulonglong2*)h_sh[cur][r];
                    u64 ac0 = 0, ac1 = 0, ac2 = 0, ac3 = 0;
#pragma unroll
                    for (int q = 0; q < 12; q++) {
                        ulonglong2 v = hs[q];
                        if (q & 1) { fma2(ac2, v.x, whh2[2 * q]); fma2(ac3, v.y, whh2[2 * q + 1]); }
                        else        { fma2(ac0, v.x, whh2[2 * q]); fma2(ac1, v.y, whh2[2 * q + 1]); }
                    }
                    {
                        u64 tpair = *(const u64*)&h_sh[cur][r][48];
                        fma2(ac0, tpair, whh2[24]);
                    }
                    float2 f0 = up2(ac0), f1 = up2(ac1), f2 = up2(ac2), f3 = up2(ac3);
                    hg_sh[r][tid] = bias + ((f0.x + f0.y) + (f1.x + f1.y))
                                         + ((f2.x + f2.y) + (f3.x + f3.y));
                }
            }
        }
        __syncthreads();
        if (isC) {
            float gi = xg0[0] + hg_sh[r0][j0];
            float gf = xg0[1] + hg_sh[r0][50 + j0];
            float gg = xg0[2] + hg_sh[r0][100 + j0];
            float go = xg0[3] + hg_sh[r0][150 + j0];
            cc0 = sigm(gf) * cc0 + sigm(gi) * tanh_f(gg);
            float hh = sigm(go) * tanh_f(cc0);
            h_sh[cur ^ 1][r0][j0] = hh;
            int rho = rowBase + r0;
            if (dir == 0) g_F2[((size_t)u * 512 + rho) * 50 + j0] = hh;
            else          g_B2[((size_t)(511 - u) * 512 + rho) * 50 + j0] = hh;
        }
        __syncthreads();
#pragma unroll
        for (int g = 0; g < 4; g++) xg0[g] = nxg0[g];
        cur ^= 1;
    }
}

// ---------------------------------------------------------------------------
// Output linear (FFMA2): out[pos][n] = F2[pos]·wf[n] + B2[pos]·wb[n] + b[n]
// ---------------------------------------------------------------------------
__global__ void __launch_bounds__(256) out_kernel(
    const float* __restrict__ lin_w, const float* __restrict__ lin_b,
    float* __restrict__ out)
{
    __shared__ __align__(16) float wf_sh[45 * 52];
    __shared__ __align__(16) float wb_sh[45 * 52];
    __shared__ float b_sh[45];
    const int tid = threadIdx.x;
    for (int i = tid; i < 45 * 52; i += 256) {
        int n = i / 52, k = i - n * 52;
        wf_sh[i] = (k < 50) ? lin_w[n * 100 + k] : 0.f;
        wb_sh[i] = (k < 50) ? lin_w[n * 100 + 50 + k] : 0.f;
    }
    if (tid < 45) b_sh[tid] = lin_b[tid];
    __syncthreads();

    const int pos = blockIdx.x * 256 + tid;
    float acc[45];
#pragma unroll
    for (int n = 0; n < 45; n++) acc[n] = b_sh[n];

    {
        const u64* xp = (const u64*)(g_F2 + (size_t)pos * 50);
        u64 xr2[25];
#pragma unroll
        for (int k = 0; k < 25; k++) xr2[k] = xp[k];
#pragma unroll 3
        for (int n = 0; n < 45; n++) {
            const float* w = wf_sh + n * 52;
            const ulonglong2* wv = (const ulonglong2*)w;
            u64 a = 0, b = 0;
#pragma unroll
            for (int q = 0; q < 12; q++) {
                ulonglong2 v = wv[q];
                fma2(a, xr2[2 * q], v.x);
                fma2(b, xr2[2 * q + 1], v.y);
            }
            fma2(a, xr2[24], ((const u64*)w)[24]);
            float2 fa = up2(a), fb = up2(b);
            acc[n] += (fa.x + fa.y) + (fb.x + fb.y);
        }
    }
    {
        const u64* xp = (const u64*)(g_B2 + (size_t)pos * 50);
        u64 xr2[25];
#pragma unroll
        for (int k = 0; k < 25; k++) xr2[k] = xp[k];
#pragma unroll 3
        for (int n = 0; n < 45; n++) {
            const float* w = wb_sh + n * 52;
            const ulonglong2* wv = (const ulonglong2*)w;
            u64 a = 0, b = 0;
#pragma unroll
            for (int q = 0; q < 12; q++) {
                ulonglong2 v = wv[q];
                fma2(a, xr2[2 * q], v.x);
                fma2(b, xr2[2 * q + 1], v.y);
            }
            fma2(a, xr2[24], ((const u64*)w)[24]);
            float2 fa = up2(a), fb = up2(b);
            acc[n] += (fa.x + fa.y) + (fb.x + fb.y);
        }
    }
    float* o = out + (size_t)pos * 45;
#pragma unroll
    for (int n = 0; n < 45; n++) o[n] = acc[n];
}

// ---------------------------------------------------------------------------
extern "C" void kernel_launch(void* const* d_in, const int* in_sizes, int n_in,
                              void* d_out, int out_size) {
    const int*   x       = (const int*)  d_in[0];
    const float* emb_f1  = (const float*)d_in[1];
    const float* emb_b1  = (const float*)d_in[2];
    const float* h0_f1   = (const float*)d_in[3];
    const float* c0_f1   = (const float*)d_in[4];
    const float* Wih_f1  = (const float*)d_in[5];
    const float* Whh_f1  = (const float*)d_in[6];
    const float* bih_f1  = (const float*)d_in[7];
    const float* bhh_f1  = (const float*)d_in[8];
    const float* h0_b1   = (const float*)d_in[9];
    const float* c0_b1   = (const float*)d_in[10];
    const float* Wih_b1  = (const float*)d_in[11];
    const float* Whh_b1  = (const float*)d_in[12];
    const float* bih_b1  = (const float*)d_in[13];
    const float* bhh_b1  = (const float*)d_in[14];
    const float* h0_f2   = (const float*)d_in[15];
    const float* c0_f2   = (const float*)d_in[16];
    const float* Wih_f2  = (const float*)d_in[17];
    const float* Whh_f2  = (const float*)d_in[18];
    const float* bih_f2  = (const float*)d_in[19];
    const float* bhh_f2  = (const float*)d_in[20];
    const float* h0_b2   = (const float*)d_in[21];
    const float* c0_b2   = (const float*)d_in[22];
    const float* Wih_b2  = (const float*)d_in[23];
    const float* Whh_b2  = (const float*)d_in[24];
    const float* bih_b2  = (const float*)d_in[25];
    const float* bhh_b2  = (const float*)d_in[26];
    const float* lin_w   = (const float*)d_in[27];
    const float* lin_b   = (const float*)d_in[28];
    float* out = (float*)d_out;

    int nvocab = in_sizes[1] / 20;
    if (nvocab > 50000) nvocab = 50000;
    int tg_blocks = (nvocab + 255) / 256;

    sniff_kernel<<<1, 1>>>(x);
    tokgate_kernel<<<2 * tg_blocks, 256>>>(emb_f1, Wih_f1, emb_b1, Wih_b1,
                                           tg_blocks, nvocab);
    r1_kernel<<<512, 128>>>(x,
                            h0_f1, c0_f1, Whh_f1, bih_f1, bhh_f1,
                            h0_b1, c0_b1, Whh_b1, bih_b1, bhh_b1);
    xg2_kernel<<<4096, 128>>>(Wih_f2, Wih_b2);
    r2_kernel<<<296, 224>>>(h0_f2, c0_f2, Whh_f2, bih_f2, bhh_f2,
                            h0_b2, c0_b2, Whh_b2, bih_b2, bhh_b2);
    out_kernel<<<1024, 256>>>(lin_w, lin_b, out);
}